// round 5
// baseline (speedup 1.0000x reference)
#include <cuda_runtime.h>
#include <math.h>

#define T_STEPS   8192
#define N_RES     2048
#define DIN       64
#define DOUT      64
#define NNZ_CAP   384          // 32 lanes x 12 slots (mean nnz/row ~205)
#define SLOTS     12
#define GRID_MAIN 64
#define ROWS_PER_CTA 32        // 2048 / 64
#define THREADS_MAIN 1024      // 32 warps, 1 warp per row
#define LEAK      0.3f
#define ONE_MINUS_LEAK 0.7f
#define NOISE_SCL 0.01f

// ---- device scratch (static; no allocation anywhere) ----
__device__ float    g_vals[(size_t)N_RES * NNZ_CAP];
__device__ int      g_cols[(size_t)N_RES * NNZ_CAP];
__device__ float    g_states[(size_t)T_STEPS * N_RES];       // 64 MB, streaming (readout only)
// self-signaling exchange: (value bits, step tag) pairs, double-buffered by parity
__device__ __align__(16) uint2 g_xch[2][GRID_MAIN][ROWS_PER_CTA];   // 32 KB

// ---- reset exchange tags (runs first on every graph replay) ----
__global__ void k_init() {
    int i = blockIdx.x * blockDim.x + threadIdx.x;
    if (i < 2 * GRID_MAIN * ROWS_PER_CTA) ((uint2*)g_xch)[i] = make_uint2(0u, 0u);
}

// ---- build bank-aware padded sparse rows: one warp per row ----
// lane l primarily owns columns with col%32 == l -> conflict-free smem gathers;
// overflow entries are redistributed into other lanes' free slots.
#define SPILL_CAP 128
__global__ void __launch_bounds__(256) k_build(const float* __restrict__ W) {
    __shared__ float sv[8][SPILL_CAP];
    __shared__ int   sc[8][SPILL_CAP];
    __shared__ int   sn[8];
    int wwarp = threadIdx.x >> 5;
    int lane  = threadIdx.x & 31;
    int row   = blockIdx.x * 8 + wwarp;
    if (row >= N_RES) return;
    if (lane == 0) sn[wwarp] = 0;
    __syncwarp();

    const float* wr = W + (size_t)row * N_RES;
    float* vd = g_vals + (size_t)row * NNZ_CAP;
    int*   cd = g_cols + (size_t)row * NNZ_CAP;

    int cnt = 0;
    for (int base = 0; base < N_RES / 32; base++) {
        int col = base * 32 + lane;
        float v = wr[col];
        if (v != 0.0f) {
            if (cnt < SLOTS) { vd[lane * SLOTS + cnt] = v; cd[lane * SLOTS + cnt] = col; cnt++; }
            else {
                int p = atomicAdd(&sn[wwarp], 1);
                if (p < SPILL_CAP) { sv[wwarp][p] = v; sc[wwarp][p] = col; }
            }
        }
    }
    __syncwarp();
    int freecnt = SLOTS - cnt;
    int pfx = freecnt;
    #pragma unroll
    for (int o = 1; o < 32; o <<= 1) {
        int nv = __shfl_up_sync(0xffffffffu, pfx, o);
        if (lane >= o) pfx += nv;
    }
    int excl = pfx - freecnt;
    int ns = sn[wwarp]; if (ns > SPILL_CAP) ns = SPILL_CAP;
    for (int k = 0; k < freecnt; k++) {
        int idx = excl + k;
        if (idx < ns) { vd[lane * SLOTS + cnt + k] = sv[wwarp][idx]; cd[lane * SLOTS + cnt + k] = sc[wwarp][idx]; }
        else          { vd[lane * SLOTS + cnt + k] = 0.0f;           cd[lane * SLOTS + cnt + k] = lane; }
    }
}

// ---- persistent recurrence: self-signaling (value,tag) exchange, import == barrier ----
__global__ void __launch_bounds__(THREADS_MAIN, 1)
k_reservoir(const float* __restrict__ u,
            const float* __restrict__ noise,
            const float* __restrict__ W_in) {
    __shared__ float s_smem[N_RES];
    __shared__ float u_s[2][DIN];

    const int tid  = threadIdx.x;
    const int lane = tid & 31;
    const int w    = tid >> 5;
    const int row  = blockIdx.x * ROWS_PER_CTA + w;

    // park this row's bank-aligned sparse slice in registers for the whole run
    float4 v4[3]; int4 c4[3];
    {
        const float4* vp = (const float4*)(g_vals + (size_t)row * NNZ_CAP + lane * SLOTS);
        const int4*   cp = (const int4*)  (g_cols + (size_t)row * NNZ_CAP + lane * SLOTS);
        #pragma unroll
        for (int c = 0; c < 3; c++) { v4[c] = vp[c]; c4[c] = cp[c]; }
    }
    const float win0 = W_in[row * DIN + lane];
    const float win1 = W_in[row * DIN + 32 + lane];

    for (int i = tid; i < N_RES; i += THREADS_MAIN) s_smem[i] = 0.0f;
    if (tid < DIN) u_s[0][tid] = u[tid];
    float noise_cur = noise[row];
    float noise_next = 0.0f;
    __syncthreads();

    for (int t = 0; t < T_STEPS; t++) {
        const int buf = t & 1;
        const int tn  = (t + 1 < T_STEPS) ? t + 1 : t;
        const unsigned target = (unsigned)(t + 1);

        // prefetch next input vector (off critical path)
        if (tid < DIN) u_s[buf ^ 1][tid] = __ldg(&u[tn * DIN + tid]);

        // drive + conflict-free sparse gathers from current state
        float acc = fmaf(win0, u_s[buf][lane], win1 * u_s[buf][lane + 32]);
        #pragma unroll
        for (int c = 0; c < 3; c++) {
            acc = fmaf(v4[c].x, s_smem[c4[c].x], acc);
            acc = fmaf(v4[c].y, s_smem[c4[c].y], acc);
            acc = fmaf(v4[c].z, s_smem[c4[c].z], acc);
            acc = fmaf(v4[c].w, s_smem[c4[c].w], acc);
        }
        #pragma unroll
        for (int o = 16; o; o >>= 1) acc += __shfl_xor_sync(0xffffffffu, acc, o);

        // lane 0 publishes its row the moment it's ready: one atomic-enough STG.64
        if (lane == 0) {
            acc += NOISE_SCL * noise_cur;
            float snew = ONE_MINUS_LEAK * s_smem[row] + LEAK * tanhf(acc);
            asm volatile("st.volatile.global.v2.u32 [%0], {%1,%2};"
                         :: "l"(&g_xch[buf][blockIdx.x][w]),
                            "r"(__float_as_uint(snew)), "r"(target) : "memory");
            __stcs(&g_states[(size_t)t * N_RES + row], snew);      // streaming, for k_out
            noise_next = __ldcs(&noise[(size_t)tn * N_RES + row]); // prefetch after publish
        }
        noise_cur = noise_next;
        __syncthreads();          // all s_smem reads done -> safe to overwrite

        // import == barrier: warp w pulls source CTAs w and w+32; a matching
        // tag inside the same 8B pair proves the value is this step's.
        {
            const uint2* p0 = &g_xch[buf][w][lane];
            const uint2* p1 = &g_xch[buf][w + 32][lane];
            uint2 d0, d1; unsigned ok0 = 0u, ok1 = 0u;
            do {
                if (!ok0) {
                    asm volatile("ld.volatile.global.v2.u32 {%0,%1}, [%2];"
                                 : "=r"(d0.x), "=r"(d0.y) : "l"(p0) : "memory");
                    ok0 = (d0.y == target);
                }
                if (!ok1) {
                    asm volatile("ld.volatile.global.v2.u32 {%0,%1}, [%2];"
                                 : "=r"(d1.x), "=r"(d1.y) : "l"(p1) : "memory");
                    ok1 = (d1.y == target);
                }
            } while (__any_sync(0xffffffffu, (ok0 & ok1) == 0u));
            s_smem[w * 32 + lane]        = __uint_as_float(d0.x);
            s_smem[(w + 32) * 32 + lane] = __uint_as_float(d1.x);
        }
        __syncthreads();          // full new state resident
    }
}

// ---- readout GEMM: out[T,64] = states @ w_out^T + b_out ----
#define KC 32
__global__ void __launch_bounds__(128, 2)
k_out(const float* __restrict__ w_out, const float* __restrict__ b_out,
      float* __restrict__ out) {
    __shared__ float sA[32][KC];
    __shared__ float sB[64][KC];
    const int tid = threadIdx.x;
    const int tx  = tid & 15;
    const int ty  = tid >> 4;
    const int t0  = blockIdx.x * 32;

    float acc[4][4];
    #pragma unroll
    for (int i = 0; i < 4; i++)
        #pragma unroll
        for (int j = 0; j < 4; j++) acc[i][j] = 0.0f;

    for (int k0 = 0; k0 < N_RES; k0 += KC) {
        #pragma unroll
        for (int it = 0; it < 2; it++) {
            int idx = tid + it * 128;
            int r = idx >> 3, kk = (idx & 7) * 4;
            *(float4*)&sA[r][kk] = *(const float4*)&g_states[(size_t)(t0 + r) * N_RES + k0 + kk];
        }
        #pragma unroll
        for (int it = 0; it < 4; it++) {
            int idx = tid + it * 128;
            int r = idx >> 3, kk = (idx & 7) * 4;
            *(float4*)&sB[r][kk] = *(const float4*)&w_out[(size_t)r * N_RES + k0 + kk];
        }
        __syncthreads();
        #pragma unroll
        for (int kk = 0; kk < KC; kk += 4) {
            float4 a[4], b[4];
            #pragma unroll
            for (int i = 0; i < 4; i++) a[i] = *(const float4*)&sA[ty * 4 + i][kk];
            #pragma unroll
            for (int j = 0; j < 4; j++) b[j] = *(const float4*)&sB[tx * 4 + j][kk];
            #pragma unroll
            for (int i = 0; i < 4; i++)
                #pragma unroll
                for (int j = 0; j < 4; j++) {
                    acc[i][j] = fmaf(a[i].x, b[j].x, acc[i][j]);
                    acc[i][j] = fmaf(a[i].y, b[j].y, acc[i][j]);
                    acc[i][j] = fmaf(a[i].z, b[j].z, acc[i][j]);
                    acc[i][j] = fmaf(a[i].w, b[j].w, acc[i][j]);
                }
        }
        __syncthreads();
    }
    #pragma unroll
    for (int i = 0; i < 4; i++)
        #pragma unroll
        for (int j = 0; j < 4; j++)
            out[(size_t)(t0 + ty * 4 + i) * DOUT + tx * 4 + j] = acc[i][j] + b_out[tx * 4 + j];
}

extern "C" void kernel_launch(void* const* d_in, const int* in_sizes, int n_in,
                              void* d_out, int out_size) {
    const float* u     = (const float*)d_in[0];
    const float* noise = (const float*)d_in[1];
    const float* W_in  = (const float*)d_in[2];
    const float* W     = (const float*)d_in[3];
    const float* w_out = (const float*)d_in[4];
    const float* b_out = (const float*)d_in[5];
    float* out = (float*)d_out;

    k_init<<<4, 1024>>>();
    k_build<<<N_RES / 8, 256>>>(W);
    k_reservoir<<<GRID_MAIN, THREADS_MAIN>>>(u, noise, W_in);
    k_out<<<T_STEPS / 32, 128>>>(w_out, b_out, out);
}